// round 1
// baseline (speedup 1.0000x reference)
#include <cuda_runtime.h>

#define Hh 200
#define Dd 768
#define BSROWS 2048   // B*S
#define SQ 512
#define NB 4

__device__ float g_Ueff[Hh * Hh];
__device__ float g_head[BSROWS * Hh];
__device__ float g_tail[BSROWS * Hh];
__device__ float g_M[BSROWS * Hh];

// ---------------------------------------------------------------------------
// Fold: Ueff[i,j] = sum_o U[o,i,j] * W_down[o]
// U is [200,200,200] row-major; for fixed o the (i,j) plane is contiguous,
// so consecutive threads read consecutive addresses -> fully coalesced.
// ---------------------------------------------------------------------------
__global__ void fold_u_kernel(const float* __restrict__ U,
                              const float* __restrict__ W_down) {
    int idx = blockIdx.x * blockDim.x + threadIdx.x;
    if (idx >= Hh * Hh) return;
    float acc = 0.f;
#pragma unroll 4
    for (int o = 0; o < Hh; ++o)
        acc = fmaf(U[o * Hh * Hh + idx], __ldg(&W_down[o]), acc);
    g_Ueff[idx] = acc;
}

// ---------------------------------------------------------------------------
// Generic NN SGEMM: C[M,N] = op(A[M,K] @ B[K,N] + bias)
// 64x64 block tile, BK=16, 256 threads, 4x4 per-thread register tile.
// ---------------------------------------------------------------------------
template <int RELU>
__global__ __launch_bounds__(256) void gemm_nn_kernel(
    const float* __restrict__ A, const float* __restrict__ Bm,
    const float* __restrict__ bias, float* __restrict__ C,
    int M, int N, int K) {
    __shared__ float As[16][64];
    __shared__ float Bs[16][68];  // padded vs bank conflicts

    int t = threadIdx.x;
    int tx = t & 15, ty = t >> 4;
    int m0 = blockIdx.y * 64;
    int n0 = blockIdx.x * 64;

    float acc[4][4] = {};

    for (int k0 = 0; k0 < K; k0 += 16) {
#pragma unroll
        for (int i = 0; i < 4; ++i) {
            int idx = t + i * 256;
            int r = idx >> 4, kk = idx & 15;
            int gm = m0 + r, gk = k0 + kk;
            As[kk][r] = (gm < M && gk < K) ? A[gm * K + gk] : 0.f;
        }
#pragma unroll
        for (int i = 0; i < 4; ++i) {
            int idx = t + i * 256;
            int kk = idx >> 6, c = idx & 63;
            int gk = k0 + kk, gn = n0 + c;
            Bs[kk][c] = (gk < K && gn < N) ? Bm[gk * N + gn] : 0.f;
        }
        __syncthreads();
#pragma unroll
        for (int kk = 0; kk < 16; ++kk) {
            float a[4], b[4];
#pragma unroll
            for (int i = 0; i < 4; ++i) a[i] = As[kk][ty * 4 + i];
#pragma unroll
            for (int j = 0; j < 4; ++j) b[j] = Bs[kk][tx * 4 + j];
#pragma unroll
            for (int i = 0; i < 4; ++i)
#pragma unroll
                for (int j = 0; j < 4; ++j)
                    acc[i][j] = fmaf(a[i], b[j], acc[i][j]);
        }
        __syncthreads();
    }

#pragma unroll
    for (int i = 0; i < 4; ++i) {
        int gm = m0 + ty * 4 + i;
        if (gm >= M) continue;
#pragma unroll
        for (int j = 0; j < 4; ++j) {
            int gn = n0 + tx * 4 + j;
            if (gn >= N) continue;
            float v = acc[i][j];
            if (bias) v += __ldg(&bias[gn]);
            if (RELU) v = fmaxf(v, 0.f);
            C[gm * N + gn] = v;
        }
    }
}

// ---------------------------------------------------------------------------
// Batched NT GEMM epilogue kernel:
// scores[b,x,y] = (M[b,x,:] . tail[b,y,:] + b_down) / sqrt(200)
// Per batch: [512,200] @ [512,200]^T -> [512,512]. 512 % 64 == 0 -> no M/N guards.
// ---------------------------------------------------------------------------
__global__ __launch_bounds__(256) void gemm_nt_scores_kernel(
    const float* __restrict__ bdown, float* __restrict__ out) {
    int b = blockIdx.z;
    const float* A = g_M + b * SQ * Hh;
    const float* Bt = g_tail + b * SQ * Hh;

    __shared__ float As[16][64];
    __shared__ float Bs[16][68];

    int t = threadIdx.x;
    int tx = t & 15, ty = t >> 4;
    int x0 = blockIdx.y * 64;
    int y0 = blockIdx.x * 64;

    float acc[4][4] = {};

    for (int k0 = 0; k0 < Hh; k0 += 16) {
#pragma unroll
        for (int i = 0; i < 4; ++i) {
            int idx = t + i * 256;
            int r = idx >> 4, kk = idx & 15;
            int gk = k0 + kk;
            As[kk][r] = (gk < Hh) ? A[(x0 + r) * Hh + gk] : 0.f;
            Bs[kk][r] = (gk < Hh) ? Bt[(y0 + r) * Hh + gk] : 0.f;
        }
        __syncthreads();
#pragma unroll
        for (int kk = 0; kk < 16; ++kk) {
            float a[4], bb[4];
#pragma unroll
            for (int i = 0; i < 4; ++i) a[i] = As[kk][ty * 4 + i];
#pragma unroll
            for (int j = 0; j < 4; ++j) bb[j] = Bs[kk][tx * 4 + j];
#pragma unroll
            for (int i = 0; i < 4; ++i)
#pragma unroll
                for (int j = 0; j < 4; ++j)
                    acc[i][j] = fmaf(a[i], bb[j], acc[i][j]);
        }
        __syncthreads();
    }

    float bd = __ldg(bdown);
    const float rs = 0.070710678118654752f;  // 1/sqrt(200)
#pragma unroll
    for (int i = 0; i < 4; ++i) {
        int gx = x0 + ty * 4 + i;
#pragma unroll
        for (int j = 0; j < 4; ++j) {
            int gy = y0 + tx * 4 + j;
            out[b * SQ * SQ + gx * SQ + gy] = (acc[i][j] + bd) * rs;
        }
    }
}

// ---------------------------------------------------------------------------
// kernel_launch: 5 launches on the default stream (all graph-capturable).
// Inputs (metadata order): x, W_head, b_head, W_tail, b_tail, U, W_down, b_down
// ---------------------------------------------------------------------------
extern "C" void kernel_launch(void* const* d_in, const int* in_sizes, int n_in,
                              void* d_out, int out_size) {
    const float* x      = (const float*)d_in[0];
    const float* W_head = (const float*)d_in[1];
    const float* b_head = (const float*)d_in[2];
    const float* W_tail = (const float*)d_in[3];
    const float* b_tail = (const float*)d_in[4];
    const float* U      = (const float*)d_in[5];
    const float* W_down = (const float*)d_in[6];
    const float* b_down = (const float*)d_in[7];
    float* out = (float*)d_out;

    // device pointers to __device__ scratch (symbols referenced in-kernel; for
    // gemm_nn we need raw pointers -> fetch once per launch via kernels that
    // take them implicitly is not possible, so use cudaGetSymbolAddress-free
    // trick: pass via a small helper. Simplest: grab addresses with
    // cudaGetSymbolAddress (host-side, not a stream op, capture-safe).
    static float* p_Ueff = nullptr;
    static float* p_head = nullptr;
    static float* p_tail = nullptr;
    static float* p_M = nullptr;
    if (!p_Ueff) {
        cudaGetSymbolAddress((void**)&p_Ueff, g_Ueff);
        cudaGetSymbolAddress((void**)&p_head, g_head);
        cudaGetSymbolAddress((void**)&p_tail, g_tail);
        cudaGetSymbolAddress((void**)&p_M, g_M);
    }

    // 1) Fold U with W_down -> Ueff [200,200]
    fold_u_kernel<<<(Hh * Hh + 255) / 256, 256>>>(U, W_down);

    // 2) head = relu(x @ W_head + b_head), tail = relu(x @ W_tail + b_tail)
    dim3 gproj((Hh + 63) / 64, (BSROWS + 63) / 64);
    gemm_nn_kernel<1><<<gproj, 256>>>(x, W_head, b_head, p_head, BSROWS, Hh, Dd);
    gemm_nn_kernel<1><<<gproj, 256>>>(x, W_tail, b_tail, p_tail, BSROWS, Hh, Dd);

    // 3) M = head @ Ueff   [2048,200] @ [200,200]
    dim3 gm((Hh + 63) / 64, (BSROWS + 63) / 64);
    gemm_nn_kernel<0><<<gm, 256>>>(p_head, p_Ueff, nullptr, p_M, BSROWS, Hh, Hh);

    // 4) scores[b] = (M_b @ tail_b^T + b_down) / sqrt(200)
    dim3 gs(SQ / 64, SQ / 64, NB);
    gemm_nt_scores_kernel<<<gs, 256>>>(b_down, out);
}

// round 2
// speedup vs baseline: 1.6377x; 1.6377x over previous
#include <cuda_runtime.h>

#define Hh 200
#define Dd 768
#define BSROWS 2048   // B*S
#define SQ 512
#define NB 4
#define HH2 (Hh * Hh)

__device__ float g_Ueff[HH2];
__device__ float g_head[BSROWS * Hh];
__device__ float g_tail[BSROWS * Hh];
__device__ float g_M[BSROWS * Hh];

// ---------------------------------------------------------------------------
// Zero Ueff (needed before atomic fold)
// ---------------------------------------------------------------------------
__global__ void zero_ueff_kernel() {
    int idx = blockIdx.x * 256 + threadIdx.x;
    if (idx < HH2) g_Ueff[idx] = 0.f;
}

// ---------------------------------------------------------------------------
// Fold: Ueff[i,j] = sum_o U[o,i,j] * W_down[o], o split 8 ways (25 each),
// fully unrolled with 5 independent accumulators -> MLP ~25.
// ---------------------------------------------------------------------------
__global__ void fold_u_kernel(const float* __restrict__ U,
                              const float* __restrict__ W_down) {
    int idx = blockIdx.x * 256 + threadIdx.x;
    if (idx >= HH2) return;
    int o0 = blockIdx.y * 25;
    const float* p = U + (size_t)o0 * HH2 + idx;
    const float* w = W_down + o0;
    float a0 = 0.f, a1 = 0.f, a2 = 0.f, a3 = 0.f, a4 = 0.f;
#pragma unroll
    for (int u = 0; u < 25; u += 5) {
        a0 = fmaf(p[(size_t)(u + 0) * HH2], __ldg(w + u + 0), a0);
        a1 = fmaf(p[(size_t)(u + 1) * HH2], __ldg(w + u + 1), a1);
        a2 = fmaf(p[(size_t)(u + 2) * HH2], __ldg(w + u + 2), a2);
        a3 = fmaf(p[(size_t)(u + 3) * HH2], __ldg(w + u + 3), a3);
        a4 = fmaf(p[(size_t)(u + 4) * HH2], __ldg(w + u + 4), a4);
    }
    atomicAdd(&g_Ueff[idx], ((a0 + a1) + (a2 + a3)) + a4);
}

// ---------------------------------------------------------------------------
// Shared inner compute: 16 k-steps, 4x4 per-thread tile, float4 LDS.
// ---------------------------------------------------------------------------
#define COMPUTE_TILE(ASB, BSB)                                           \
    do {                                                                 \
        _Pragma("unroll") for (int kk = 0; kk < 16; ++kk) {              \
            float4 av = *(const float4*)&(ASB)[kk][ty * 4];              \
            float4 bv = *(const float4*)&(BSB)[kk][tx * 4];              \
            float aa[4] = {av.x, av.y, av.z, av.w};                      \
            float bb[4] = {bv.x, bv.y, bv.z, bv.w};                      \
            _Pragma("unroll") for (int i = 0; i < 4; ++i)                \
                _Pragma("unroll") for (int j = 0; j < 4; ++j)            \
                    acc[i][j] = fmaf(aa[i], bb[j], acc[i][j]);           \
        }                                                                \
    } while (0)

#define STORE_A_T(ASB, v)                                                \
    do {                                                                 \
        (ASB)[ak + 0][ar] = (v).x;                                       \
        (ASB)[ak + 1][ar] = (v).y;                                       \
        (ASB)[ak + 2][ar] = (v).z;                                       \
        (ASB)[ak + 3][ar] = (v).w;                                       \
    } while (0)

// ---------------------------------------------------------------------------
// Fused projection: [2048x768] @ [768x400] where cols 0..199 = W_head,
// 200..399 = W_tail. Bias + ReLU epilogue, writes g_head / g_tail.
// Double-buffered, 64x64 tile, BK=16, 256 threads, 4x4 regs.
// ---------------------------------------------------------------------------
__global__ __launch_bounds__(256) void proj_kernel(
    const float* __restrict__ x,
    const float* __restrict__ Wh, const float* __restrict__ bh,
    const float* __restrict__ Wt, const float* __restrict__ bt) {
    __shared__ float As[2][16][68];
    __shared__ float Bs[2][16][68];
    const int t = threadIdx.x;
    const int tx = t & 15, ty = t >> 4;
    const int m0 = blockIdx.y * 64;
    const int n0 = blockIdx.x * 64;
    const int ar = t >> 2, ak = (t & 3) * 4;  // A: row ar, k ak..ak+3
    const int bk = t >> 4, bc = (t & 15) * 4; // B: k bk, col bc..bc+3

    const int gn = n0 + bc;
    const float* Bbase =
        (gn < Hh) ? (Wh + gn) : ((gn < 2 * Hh) ? (Wt + (gn - Hh)) : nullptr);
    const float* Arow = x + (size_t)(m0 + ar) * Dd;
    const float4 z4 = make_float4(0.f, 0.f, 0.f, 0.f);

    float acc[4][4] = {};
    float4 a_st = *(const float4*)(Arow + ak);
    float4 b_st = Bbase ? *(const float4*)(Bbase + (size_t)bk * Hh) : z4;
    STORE_A_T(As[0], a_st);
    *(float4*)&Bs[0][bk][bc] = b_st;
    __syncthreads();

    int buf = 0;
    for (int k0 = 16; k0 < Dd; k0 += 16) {
        a_st = *(const float4*)(Arow + k0 + ak);
        b_st = Bbase ? *(const float4*)(Bbase + (size_t)(k0 + bk) * Hh) : z4;
        COMPUTE_TILE(As[buf], Bs[buf]);
        int nb = buf ^ 1;
        STORE_A_T(As[nb], a_st);
        *(float4*)&Bs[nb][bk][bc] = b_st;
        __syncthreads();
        buf = nb;
    }
    COMPUTE_TILE(As[buf], Bs[buf]);

#pragma unroll
    for (int i = 0; i < 4; ++i) {
        int gm = m0 + ty * 4 + i;
#pragma unroll
        for (int j = 0; j < 4; ++j) {
            int gc = n0 + tx * 4 + j;
            if (gc < Hh) {
                g_head[(size_t)gm * Hh + gc] =
                    fmaxf(acc[i][j] + __ldg(&bh[gc]), 0.f);
            } else if (gc < 2 * Hh) {
                int c = gc - Hh;
                g_tail[(size_t)gm * Hh + c] =
                    fmaxf(acc[i][j] + __ldg(&bt[c]), 0.f);
            }
        }
    }
}

// ---------------------------------------------------------------------------
// M = g_head @ g_Ueff : [2048x200] @ [200x200] -> g_M. Double-buffered.
// ---------------------------------------------------------------------------
__global__ __launch_bounds__(256) void gemm_m_kernel() {
    __shared__ float As[2][16][68];
    __shared__ float Bs[2][16][68];
    const int t = threadIdx.x;
    const int tx = t & 15, ty = t >> 4;
    const int m0 = blockIdx.y * 64;
    const int n0 = blockIdx.x * 64;
    const int ar = t >> 2, ak = (t & 3) * 4;
    const int bk = t >> 4, bc = (t & 15) * 4;
    const int gn = n0 + bc;
    const bool nok = (gn + 4 <= Hh);
    const float* Arow = g_head + (size_t)(m0 + ar) * Hh;
    const float4 z4 = make_float4(0.f, 0.f, 0.f, 0.f);

    float acc[4][4] = {};
    float4 a_st = *(const float4*)(Arow + ak);  // k0=0: ak+4 <= 16 <= 200 ok
    float4 b_st = nok ? *(const float4*)(g_Ueff + (size_t)bk * Hh + gn) : z4;
    STORE_A_T(As[0], a_st);
    *(float4*)&Bs[0][bk][bc] = b_st;
    __syncthreads();

    int buf = 0;
    const int KT = (Hh + 15) / 16;  // 13
#pragma unroll 1
    for (int kt = 1; kt < KT; ++kt) {
        int k0 = kt * 16;
        a_st = (k0 + ak + 4 <= Hh) ? *(const float4*)(Arow + k0 + ak) : z4;
        b_st = (nok && (k0 + bk) < Hh)
                   ? *(const float4*)(g_Ueff + (size_t)(k0 + bk) * Hh + gn)
                   : z4;
        COMPUTE_TILE(As[buf], Bs[buf]);
        int nb = buf ^ 1;
        STORE_A_T(As[nb], a_st);
        *(float4*)&Bs[nb][bk][bc] = b_st;
        __syncthreads();
        buf = nb;
    }
    COMPUTE_TILE(As[buf], Bs[buf]);

#pragma unroll
    for (int i = 0; i < 4; ++i) {
        int gm = m0 + ty * 4 + i;
#pragma unroll
        for (int j = 0; j < 4; ++j) {
            int gc = n0 + tx * 4 + j;
            if (gc < Hh) g_M[(size_t)gm * Hh + gc] = acc[i][j];
        }
    }
}

// ---------------------------------------------------------------------------
// scores[b,x,y] = (M[b,x,:] . tail[b,y,:] + b_down) / sqrt(200)
// Batched NT, 64x64 tile, double-buffered. 512%64==0 -> no MN guards.
// ---------------------------------------------------------------------------
__global__ __launch_bounds__(256) void gemm_nt_scores_kernel(
    const float* __restrict__ bdown, float* __restrict__ out) {
    const int b = blockIdx.z;
    const float* A = g_M + (size_t)b * SQ * Hh;
    const float* Bt = g_tail + (size_t)b * SQ * Hh;

    __shared__ float As[2][16][68];
    __shared__ float Bs[2][16][68];
    const int t = threadIdx.x;
    const int tx = t & 15, ty = t >> 4;
    const int x0 = blockIdx.y * 64;
    const int y0 = blockIdx.x * 64;
    const int ar = t >> 2, ak = (t & 3) * 4;
    const float* Arow = A + (size_t)(x0 + ar) * Hh;
    const float* Brow = Bt + (size_t)(y0 + ar) * Hh;
    const float4 z4 = make_float4(0.f, 0.f, 0.f, 0.f);

    float acc[4][4] = {};
    float4 a_st = *(const float4*)(Arow + ak);
    float4 b_st = *(const float4*)(Brow + ak);
    STORE_A_T(As[0], a_st);
    {
        Bs[0][ak + 0][ar] = b_st.x;
        Bs[0][ak + 1][ar] = b_st.y;
        Bs[0][ak + 2][ar] = b_st.z;
        Bs[0][ak + 3][ar] = b_st.w;
    }
    __syncthreads();

    int buf = 0;
    const int KT = (Hh + 15) / 16;  // 13
#pragma unroll 1
    for (int kt = 1; kt < KT; ++kt) {
        int k0 = kt * 16;
        bool kok = (k0 + ak + 4 <= Hh);
        a_st = kok ? *(const float4*)(Arow + k0 + ak) : z4;
        b_st = kok ? *(const float4*)(Brow + k0 + ak) : z4;
        COMPUTE_TILE(As[buf], Bs[buf]);
        int nb = buf ^ 1;
        STORE_A_T(As[nb], a_st);
        Bs[nb][ak + 0][ar] = b_st.x;
        Bs[nb][ak + 1][ar] = b_st.y;
        Bs[nb][ak + 2][ar] = b_st.z;
        Bs[nb][ak + 3][ar] = b_st.w;
        __syncthreads();
        buf = nb;
    }
    COMPUTE_TILE(As[buf], Bs[buf]);

    const float bd = __ldg(bdown);
    const float rs = 0.070710678118654752f;  // 1/sqrt(200)
    float* obase = out + (size_t)b * SQ * SQ;
#pragma unroll
    for (int i = 0; i < 4; ++i) {
        int gx = x0 + ty * 4 + i;
#pragma unroll
        for (int j = 0; j < 4; ++j) {
            int gy = y0 + tx * 4 + j;
            obase[(size_t)gx * SQ + gy] = (acc[i][j] + bd) * rs;
        }
    }
}

// ---------------------------------------------------------------------------
// Inputs (metadata order): x, W_head, b_head, W_tail, b_tail, U, W_down, b_down
// ---------------------------------------------------------------------------
extern "C" void kernel_launch(void* const* d_in, const int* in_sizes, int n_in,
                              void* d_out, int out_size) {
    const float* x      = (const float*)d_in[0];
    const float* W_head = (const float*)d_in[1];
    const float* b_head = (const float*)d_in[2];
    const float* W_tail = (const float*)d_in[3];
    const float* b_tail = (const float*)d_in[4];
    const float* U      = (const float*)d_in[5];
    const float* W_down = (const float*)d_in[6];
    const float* b_down = (const float*)d_in[7];
    float* out = (float*)d_out;

    // 1) Ueff = sum_o U[o]*W_down[o]  (zero + 8-way split-o atomic fold)
    zero_ueff_kernel<<<(HH2 + 255) / 256, 256>>>();
    fold_u_kernel<<<dim3((HH2 + 255) / 256, 8), 256>>>(U, W_down);

    // 2) head/tail = relu(x @ [W_head|W_tail] + bias)   (fused, N=400)
    proj_kernel<<<dim3(7, BSROWS / 64), 256>>>(x, W_head, b_head, W_tail,
                                               b_tail);

    // 3) M = head @ Ueff
    gemm_m_kernel<<<dim3((Hh + 63) / 64, BSROWS / 64), 256>>>();

    // 4) scores = (M @ tail^T + b_down) / sqrt(200)
    gemm_nt_scores_kernel<<<dim3(SQ / 64, SQ / 64, NB), 256>>>(b_down, out);
}

// round 3
// speedup vs baseline: 2.4066x; 1.4695x over previous
#include <cuda_runtime.h>
#include <cuda_bf16.h>

#define Hh 200
#define Dd 768
#define BSROWS 2048   // B*S
#define SQ 512
#define NB 4
#define HH2 (Hh * Hh)
#define KP 224        // padded K for the H-sized contraction dims (7 * 32)
#define NPW 448       // padded N rows for Wt (7 * 64)
#define NPU 256       // padded N rows for Ut (4 * 64)

// ---------------------------------------------------------------------------
// Scratch (all __device__ globals; no allocation)
// ---------------------------------------------------------------------------
__device__ float g_Ueff[HH2];
__device__ __nv_bfloat16 g_xhi[BSROWS * Dd], g_xlo[BSROWS * Dd];
__device__ __nv_bfloat16 g_Wthi[NPW * Dd], g_Wtlo[NPW * Dd];
__device__ __nv_bfloat16 g_Uthi[NPU * KP], g_Utlo[NPU * KP];
__device__ __nv_bfloat16 g_hhi[BSROWS * KP], g_hlo[BSROWS * KP];
__device__ __nv_bfloat16 g_thi[BSROWS * KP], g_tlo[BSROWS * KP];
__device__ __nv_bfloat16 g_Mhi[BSROWS * KP], g_Mlo[BSROWS * KP];

__device__ __forceinline__ void bsplit(float v, __nv_bfloat16& h,
                                       __nv_bfloat16& l) {
    h = __float2bfloat16(v);
    l = __float2bfloat16(v - __bfloat162float(h));
}

// ---------------------------------------------------------------------------
// Prep kernels
// ---------------------------------------------------------------------------
__global__ void zero_ueff_kernel() {
    int idx = blockIdx.x * 256 + threadIdx.x;
    if (idx < HH2) g_Ueff[idx] = 0.f;
}

// Ueff[i,j] = sum_o U[o,i,j] * W_down[o], o split 8 ways, MLP ~25.
__global__ void fold_u_kernel(const float* __restrict__ U,
                              const float* __restrict__ W_down) {
    int idx = blockIdx.x * 256 + threadIdx.x;
    if (idx >= HH2) return;
    int o0 = blockIdx.y * 25;
    const float* p = U + (size_t)o0 * HH2 + idx;
    const float* w = W_down + o0;
    float a0 = 0.f, a1 = 0.f, a2 = 0.f, a3 = 0.f, a4 = 0.f;
#pragma unroll
    for (int u = 0; u < 25; u += 5) {
        a0 = fmaf(p[(size_t)(u + 0) * HH2], __ldg(w + u + 0), a0);
        a1 = fmaf(p[(size_t)(u + 1) * HH2], __ldg(w + u + 1), a1);
        a2 = fmaf(p[(size_t)(u + 2) * HH2], __ldg(w + u + 2), a2);
        a3 = fmaf(p[(size_t)(u + 3) * HH2], __ldg(w + u + 3), a3);
        a4 = fmaf(p[(size_t)(u + 4) * HH2], __ldg(w + u + 4), a4);
    }
    atomicAdd(&g_Ueff[idx], ((a0 + a1) + (a2 + a3)) + a4);
}

// x [2048,768] fp32 -> hi/lo bf16 planes (same layout). 8 elems/thread.
__global__ void split_x_kernel(const float* __restrict__ x) {
    int i = blockIdx.x * 256 + threadIdx.x;
    if (i >= BSROWS * Dd / 8) return;
    const float4* p = (const float4*)x + (size_t)i * 2;
    float4 f0 = p[0], f1 = p[1];
    float v[8] = {f0.x, f0.y, f0.z, f0.w, f1.x, f1.y, f1.z, f1.w};
    union { __nv_bfloat16 h[8]; uint4 u; } H, L;
#pragma unroll
    for (int j = 0; j < 8; ++j) bsplit(v[j], H.h[j], L.h[j]);
    *(uint4*)(g_xhi + (size_t)i * 8) = H.u;
    *(uint4*)(g_xlo + (size_t)i * 8) = L.u;
}

// W_head/W_tail [768,200] -> Wt hi/lo [448,768] ([n][k], zero-padded rows).
__global__ void split_w_kernel(const float* __restrict__ Wh,
                               const float* __restrict__ Wt) {
    int gid = blockIdx.x * 256 + threadIdx.x;
    if (gid >= Dd * NPW) return;
    int k = gid / NPW, n = gid % NPW;  // read coalesced along n
    float v = 0.f;
    if (n < Hh) v = Wh[(size_t)k * Hh + n];
    else if (n < 2 * Hh) v = Wt[(size_t)k * Hh + (n - Hh)];
    __nv_bfloat16 h, l;
    bsplit(v, h, l);
    g_Wthi[(size_t)n * Dd + k] = h;
    g_Wtlo[(size_t)n * Dd + k] = l;
}

// Ueff [k=i][n=j] -> Ut hi/lo [256,224] ([n][k], zero-padded)
__global__ void split_ut_kernel() {
    int gid = blockIdx.x * 256 + threadIdx.x;
    if (gid >= NPU * KP) return;
    int n = gid / KP, k = gid % KP;
    float v = (n < Hh && k < Hh) ? g_Ueff[(size_t)k * Hh + n] : 0.f;
    __nv_bfloat16 h, l;
    bsplit(v, h, l);
    g_Uthi[gid] = h;
    g_Utlo[gid] = l;
}

// head planes: zero k-pad cols 200..223 (proj never writes them)
__global__ void zero_hpad_kernel() {
    int gid = blockIdx.x * 256 + threadIdx.x;
    if (gid >= BSROWS * (KP - Hh)) return;
    int row = gid / (KP - Hh), c = Hh + gid % (KP - Hh);
    g_hhi[(size_t)row * KP + c] = __float2bfloat16(0.f);
    g_hlo[(size_t)row * KP + c] = __float2bfloat16(0.f);
}

// ---------------------------------------------------------------------------
// MMA primitives
// ---------------------------------------------------------------------------
__device__ __forceinline__ void ldsm4(unsigned r[4], unsigned a) {
    asm volatile(
        "ldmatrix.sync.aligned.m8n8.x4.shared.b16 {%0,%1,%2,%3}, [%4];\n"
        : "=r"(r[0]), "=r"(r[1]), "=r"(r[2]), "=r"(r[3])
        : "r"(a));
}
__device__ __forceinline__ void mma_bf16(float c[4], const unsigned a[4],
                                         const unsigned b[2]) {
    asm volatile(
        "mma.sync.aligned.m16n8k16.row.col.f32.bf16.bf16.f32 "
        "{%0,%1,%2,%3}, {%4,%5,%6,%7}, {%8,%9}, {%0,%1,%2,%3};\n"
        : "+f"(c[0]), "+f"(c[1]), "+f"(c[2]), "+f"(c[3])
        : "r"(a[0]), "r"(a[1]), "r"(a[2]), "r"(a[3]), "r"(b[0]), "r"(b[1]));
}

// XOR swizzle: rows are 64B (BK=32 bf16). chunk = 16B unit index (0..3).
__device__ __forceinline__ unsigned swz(int row, int c) {
    return (unsigned)(row * 64 + ((c ^ ((row >> 1) & 3)) << 4));
}

// ---------------------------------------------------------------------------
// Unified bf16x3 MMA GEMM.  C[M,64-tile] = Ahi*Bhi + Ahi*Blo + Alo*Bhi
// A gmem: row-major [m][k] (hi/lo planes), B gmem: [n][k] (hi/lo planes).
// MODE 0: proj epilogue (bias+relu -> split to g_h*/g_t*)
// MODE 1: gemm_m epilogue (split to g_M*, zero k-pad)
// MODE 2: scores epilogue ((v + bd) / sqrt(200) -> fp32 out, batched by z)
// ---------------------------------------------------------------------------
template <int BM, int MODE>
__global__ __launch_bounds__(256) void mma_gemm_kernel(
    const __nv_bfloat16* __restrict__ Ahi, const __nv_bfloat16* __restrict__ Alo,
    int lda,
    const __nv_bfloat16* __restrict__ Bhi, const __nv_bfloat16* __restrict__ Blo,
    int ldb, int ktiles,
    const float* __restrict__ bias_h, const float* __restrict__ bias_t,
    float* __restrict__ outf, const float* __restrict__ bdown) {
    constexpr int WM = BM / 32;       // warps along M
    constexpr int WN = 8 / WM;        // warps along N
    constexpr int WNT = 64 / WN;      // per-warp N extent (32 or 16)
    constexpr int NSUB = WNT / 8;     // n8 tiles per warp (4 or 2)
    constexpr int ABYTES = BM * 64;   // per plane per stage
    constexpr int BBYTES = 64 * 64;
    constexpr int STAGE = 2 * ABYTES + 2 * BBYTES;
    constexpr int A_TOT = 2 * BM * 4;  // uint4 chunks, both planes
    constexpr int A_IT = A_TOT / 256;

    __shared__ __align__(16) unsigned char smem[2 * STAGE];

    const int t = threadIdx.x;
    const int lane = t & 31, warp = t >> 5;
    const int m0 = blockIdx.y * BM;
    const int n0 = blockIdx.x * 64;
    const int wm = (warp % WM) * 32;
    const int wn = (warp / WM) * WNT;

    if (MODE == 2) {
        size_t ofs = (size_t)blockIdx.z * SQ;
        Ahi += ofs * lda; Alo += ofs * lda;
        Bhi += ofs * ldb; Blo += ofs * ldb;
    }

    // fill descriptors
    const __nv_bfloat16* aptr[A_IT];
    unsigned aoff[A_IT];
#pragma unroll
    for (int i = 0; i < A_IT; ++i) {
        int ca = t + i * 256;
        int pl = ca / (BM * 4);
        int rem = ca - pl * (BM * 4);
        int row = rem >> 2, c = rem & 3;
        aptr[i] = (pl ? Alo : Ahi) + (size_t)(m0 + row) * lda + c * 8;
        aoff[i] = pl * ABYTES + swz(row, c);
    }
    const __nv_bfloat16* bptr[2];
    unsigned boff[2];
#pragma unroll
    for (int i = 0; i < 2; ++i) {
        int cb = t + i * 256;
        int pl = cb >> 8;
        int rem = cb & 255;
        int row = rem >> 2, c = rem & 3;
        bptr[i] = (pl ? Blo : Bhi) + (size_t)(n0 + row) * ldb + c * 8;
        boff[i] = 2 * ABYTES + pl * BBYTES + swz(row, c);
    }

    const unsigned sbase = (unsigned)__cvta_generic_to_shared(smem);
    float acc[2][NSUB][4];
#pragma unroll
    for (int mi = 0; mi < 2; ++mi)
#pragma unroll
        for (int ni = 0; ni < NSUB; ++ni)
#pragma unroll
            for (int r = 0; r < 4; ++r) acc[mi][ni][r] = 0.f;

    uint4 ra[A_IT], rb[2];
#pragma unroll
    for (int i = 0; i < A_IT; ++i) ra[i] = *(const uint4*)aptr[i];
#pragma unroll
    for (int i = 0; i < 2; ++i) rb[i] = *(const uint4*)bptr[i];
#pragma unroll
    for (int i = 0; i < A_IT; ++i) *(uint4*)(smem + aoff[i]) = ra[i];
#pragma unroll
    for (int i = 0; i < 2; ++i) *(uint4*)(smem + boff[i]) = rb[i];
    __syncthreads();

    auto compute = [&](int buf) {
        unsigned bb = sbase + buf * STAGE;
#pragma unroll
        for (int s = 0; s < 2; ++s) {
            unsigned ah[2][4], al[2][4], bh[NSUB][2], bl[NSUB][2];
            {
                int row0 = wm + (lane & 15);
                int c = 2 * s + (lane >> 4);
#pragma unroll
                for (int mi = 0; mi < 2; ++mi) {
                    unsigned sa = swz(row0 + mi * 16, c);
                    ldsm4(ah[mi], bb + sa);
                    ldsm4(al[mi], bb + ABYTES + sa);
                }
            }
            {
                int rbase = wn + (lane & 7) + ((lane >> 4) << 3);
                int c = 2 * s + ((lane >> 3) & 1);
#pragma unroll
                for (int p = 0; p < NSUB / 2; ++p) {
                    unsigned sb = swz(rbase + p * 16, c);
                    unsigned tmp[4];
                    ldsm4(tmp, bb + 2 * ABYTES + sb);
                    bh[2 * p][0] = tmp[0]; bh[2 * p][1] = tmp[1];
                    bh[2 * p + 1][0] = tmp[2]; bh[2 * p + 1][1] = tmp[3];
                    ldsm4(tmp, bb + 2 * ABYTES + BBYTES + sb);
                    bl[2 * p][0] = tmp[0]; bl[2 * p][1] = tmp[1];
                    bl[2 * p + 1][0] = tmp[2]; bl[2 * p + 1][1] = tmp[3];
                }
            }
#pragma unroll
            for (int mi = 0; mi < 2; ++mi)
#pragma unroll
                for (int ni = 0; ni < NSUB; ++ni)
                    mma_bf16(acc[mi][ni], ah[mi], bh[ni]);
#pragma unroll
            for (int mi = 0; mi < 2; ++mi)
#pragma unroll
                for (int ni = 0; ni < NSUB; ++ni)
                    mma_bf16(acc[mi][ni], ah[mi], bl[ni]);
#pragma unroll
            for (int mi = 0; mi < 2; ++mi)
#pragma unroll
                for (int ni = 0; ni < NSUB; ++ni)
                    mma_bf16(acc[mi][ni], al[mi], bh[ni]);
        }
    };

    int buf = 0;
#pragma unroll 1
    for (int kt = 1; kt < ktiles; ++kt) {
#pragma unroll
        for (int i = 0; i < A_IT; ++i)
            ra[i] = *(const uint4*)(aptr[i] + kt * 32);
#pragma unroll
        for (int i = 0; i < 2; ++i)
            rb[i] = *(const uint4*)(bptr[i] + kt * 32);
        compute(buf);
        int nb = buf ^ 1;
        unsigned sb = nb * STAGE;
#pragma unroll
        for (int i = 0; i < A_IT; ++i) *(uint4*)(smem + sb + aoff[i]) = ra[i];
#pragma unroll
        for (int i = 0; i < 2; ++i) *(uint4*)(smem + sb + boff[i]) = rb[i];
        __syncthreads();
        buf = nb;
    }
    compute(buf);

    // ---------------- epilogue ----------------
    const float rs = 0.070710678118654752f;
    float bd = 0.f;
    if (MODE == 2) bd = __ldg(bdown);

#pragma unroll
    for (int mi = 0; mi < 2; ++mi) {
#pragma unroll
        for (int ni = 0; ni < NSUB; ++ni) {
#pragma unroll
            for (int rp = 0; rp < 2; ++rp) {
                int row = m0 + wm + mi * 16 + (lane >> 2) + rp * 8;
                int col = n0 + wn + ni * 8 + 2 * (lane & 3);
                float v0 = acc[mi][ni][rp * 2];
                float v1 = acc[mi][ni][rp * 2 + 1];
                if (MODE == 0) {
                    if (col < Hh) {
                        v0 = fmaxf(v0 + __ldg(&bias_h[col]), 0.f);
                        v1 = fmaxf(v1 + __ldg(&bias_h[col + 1]), 0.f);
                        __nv_bfloat16 h0, l0, h1, l1;
                        bsplit(v0, h0, l0);
                        bsplit(v1, h1, l1);
                        size_t o = (size_t)row * KP + col;
                        *(__nv_bfloat162*)(g_hhi + o) = __halves2bfloat162(h0, h1);
                        *(__nv_bfloat162*)(g_hlo + o) = __halves2bfloat162(l0, l1);
                    } else {
                        int c = col - Hh;
                        if (c < KP) {
                            if (col < 2 * Hh) {
                                v0 = fmaxf(v0 + __ldg(&bias_t[c]), 0.f);
                                v1 = fmaxf(v1 + __ldg(&bias_t[c + 1]), 0.f);
                            } else {
                                v0 = 0.f;
                                v1 = 0.f;
                            }
                            __nv_bfloat16 h0, l0, h1, l1;
                            bsplit(v0, h0, l0);
                            bsplit(v1, h1, l1);
                            size_t o = (size_t)row * KP + c;
                            *(__nv_bfloat162*)(g_thi + o) =
                                __halves2bfloat162(h0, h1);
                            *(__nv_bfloat162*)(g_tlo + o) =
                                __halves2bfloat162(l0, l1);
                        }
                    }
                } else if (MODE == 1) {
                    if (col < KP) {
                        if (col >= Hh) { v0 = 0.f; v1 = 0.f; }
                        __nv_bfloat16 h0, l0, h1, l1;
                        bsplit(v0, h0, l0);
                        bsplit(v1, h1, l1);
                        size_t o = (size_t)row * KP + col;
                        *(__nv_bfloat162*)(g_Mhi + o) = __halves2bfloat162(h0, h1);
                        *(__nv_bfloat162*)(g_Mlo + o) = __halves2bfloat162(l0, l1);
                    }
                } else {
                    float2 o;
                    o.x = (v0 + bd) * rs;
                    o.y = (v1 + bd) * rs;
                    *(float2*)(outf + (size_t)blockIdx.z * SQ * SQ +
                               (size_t)row * SQ + col) = o;
                }
            }
        }
    }
}

// ---------------------------------------------------------------------------
// Inputs (metadata order): x, W_head, b_head, W_tail, b_tail, U, W_down, b_down
// ---------------------------------------------------------------------------
extern "C" void kernel_launch(void* const* d_in, const int* in_sizes, int n_in,
                              void* d_out, int out_size) {
    const float* x      = (const float*)d_in[0];
    const float* W_head = (const float*)d_in[1];
    const float* b_head = (const float*)d_in[2];
    const float* W_tail = (const float*)d_in[3];
    const float* b_tail = (const float*)d_in[4];
    const float* U      = (const float*)d_in[5];
    const float* W_down = (const float*)d_in[6];
    const float* b_down = (const float*)d_in[7];
    float* out = (float*)d_out;

    static __nv_bfloat16 *p_xhi, *p_xlo, *p_Wthi, *p_Wtlo, *p_Uthi, *p_Utlo;
    static __nv_bfloat16 *p_hhi, *p_hlo, *p_thi, *p_tlo, *p_Mhi, *p_Mlo;
    static bool init = false;
    if (!init) {
        cudaGetSymbolAddress((void**)&p_xhi, g_xhi);
        cudaGetSymbolAddress((void**)&p_xlo, g_xlo);
        cudaGetSymbolAddress((void**)&p_Wthi, g_Wthi);
        cudaGetSymbolAddress((void**)&p_Wtlo, g_Wtlo);
        cudaGetSymbolAddress((void**)&p_Uthi, g_Uthi);
        cudaGetSymbolAddress((void**)&p_Utlo, g_Utlo);
        cudaGetSymbolAddress((void**)&p_hhi, g_hhi);
        cudaGetSymbolAddress((void**)&p_hlo, g_hlo);
        cudaGetSymbolAddress((void**)&p_thi, g_thi);
        cudaGetSymbolAddress((void**)&p_tlo, g_tlo);
        cudaGetSymbolAddress((void**)&p_Mhi, g_Mhi);
        cudaGetSymbolAddress((void**)&p_Mlo, g_Mlo);
        init = true;
    }

    // prep
    zero_ueff_kernel<<<(HH2 + 255) / 256, 256>>>();
    fold_u_kernel<<<dim3((HH2 + 255) / 256, 8), 256>>>(U, W_down);
    split_x_kernel<<<BSROWS * Dd / 8 / 256, 256>>>(x);
    split_w_kernel<<<(Dd * NPW + 255) / 256, 256>>>(W_head, W_tail);
    split_ut_kernel<<<(NPU * KP + 255) / 256, 256>>>();
    zero_hpad_kernel<<<(BSROWS * (KP - Hh) + 255) / 256, 256>>>();

    // proj: [2048x768] x [448x768]^T -> head/tail (bias+relu, split)
    mma_gemm_kernel<128, 0><<<dim3(NPW / 64, BSROWS / 128), 256>>>(
        p_xhi, p_xlo, Dd, p_Wthi, p_Wtlo, Dd, Dd / 32, b_head, b_tail,
        nullptr, nullptr);

    // M = head @ Ueff : [2048x224] x [256x224]^T
    mma_gemm_kernel<64, 1><<<dim3(NPU / 64, BSROWS / 64), 256>>>(
        p_hhi, p_hlo, KP, p_Uthi, p_Utlo, KP, KP / 32, nullptr, nullptr,
        nullptr, nullptr);

    // scores[b] = (M_b @ tail_b^T + b_down) / sqrt(200)
    mma_gemm_kernel<128, 2><<<dim3(SQ / 64, SQ / 128, NB), 256>>>(
        p_Mhi, p_Mlo, KP, p_thi, p_tlo, KP, KP / 32, nullptr, nullptr, out,
        b_down);
}

// round 4
// speedup vs baseline: 2.7514x; 1.1433x over previous
#include <cuda_runtime.h>
#include <cuda_bf16.h>

#define Hh 200
#define Dd 768
#define BSROWS 2048   // B*S
#define SQ 512
#define NB 4
#define HH2 (Hh * Hh)
#define KP 224        // padded K for the H-sized contraction dims (7 * 32)
#define NPW 448       // padded N rows for Wt (7 * 64)
#define NPU 256       // padded N rows for Ut (4 * 64)
#define NFOLD 8       // o-split for the U fold

// ---------------------------------------------------------------------------
// Scratch (all __device__ globals; no allocation)
// ---------------------------------------------------------------------------
__device__ float g_Upart[NFOLD * HH2];
__device__ __nv_bfloat16 g_xhi[BSROWS * Dd], g_xlo[BSROWS * Dd];
__device__ __nv_bfloat16 g_Wthi[NPW * Dd], g_Wtlo[NPW * Dd];
__device__ __nv_bfloat16 g_Uthi[NPU * KP], g_Utlo[NPU * KP];
__device__ __nv_bfloat16 g_hhi[BSROWS * KP], g_hlo[BSROWS * KP];
__device__ __nv_bfloat16 g_thi[BSROWS * KP], g_tlo[BSROWS * KP];
__device__ __nv_bfloat16 g_Mhi[BSROWS * KP], g_Mlo[BSROWS * KP];

__device__ __forceinline__ void bsplit(float v, __nv_bfloat16& h,
                                       __nv_bfloat16& l) {
    h = __float2bfloat16(v);
    l = __float2bfloat16(v - __bfloat162float(h));
}

// ---------------------------------------------------------------------------
// Fold partials: Upart[p][i,j] = sum_{o in slice p} U[o,i,j] * W_down[o]
// ---------------------------------------------------------------------------
__global__ void fold_u_kernel(const float* __restrict__ U,
                              const float* __restrict__ W_down) {
    int idx = blockIdx.x * 256 + threadIdx.x;
    if (idx >= HH2) return;
    int o0 = blockIdx.y * 25;
    const float* p = U + (size_t)o0 * HH2 + idx;
    const float* w = W_down + o0;
    float a0 = 0.f, a1 = 0.f, a2 = 0.f, a3 = 0.f, a4 = 0.f;
#pragma unroll
    for (int u = 0; u < 25; u += 5) {
        a0 = fmaf(p[(size_t)(u + 0) * HH2], __ldg(w + u + 0), a0);
        a1 = fmaf(p[(size_t)(u + 1) * HH2], __ldg(w + u + 1), a1);
        a2 = fmaf(p[(size_t)(u + 2) * HH2], __ldg(w + u + 2), a2);
        a3 = fmaf(p[(size_t)(u + 3) * HH2], __ldg(w + u + 3), a3);
        a4 = fmaf(p[(size_t)(u + 4) * HH2], __ldg(w + u + 4), a4);
    }
    g_Upart[(size_t)blockIdx.y * HH2 + idx] = ((a0 + a1) + (a2 + a3)) + a4;
}

// x [2048,768] fp32 -> hi/lo bf16 planes (same layout). 8 elems/thread.
__global__ void split_x_kernel(const float* __restrict__ x) {
    int i = blockIdx.x * 256 + threadIdx.x;
    if (i >= BSROWS * Dd / 8) return;
    const float4* p = (const float4*)x + (size_t)i * 2;
    float4 f0 = p[0], f1 = p[1];
    float v[8] = {f0.x, f0.y, f0.z, f0.w, f1.x, f1.y, f1.z, f1.w};
    union { __nv_bfloat16 h[8]; uint4 u; } H, L;
#pragma unroll
    for (int j = 0; j < 8; ++j) bsplit(v[j], H.h[j], L.h[j]);
    *(uint4*)(g_xhi + (size_t)i * 8) = H.u;
    *(uint4*)(g_xlo + (size_t)i * 8) = L.u;
}

// ---------------------------------------------------------------------------
// W transpose+split: [768,200]x2 -> [448,768] hi/lo, smem-tiled (coalesced
// on both sides). Grid (Dd/32, NPW/32), block (32,8).
// ---------------------------------------------------------------------------
__global__ void split_w_kernel(const float* __restrict__ Wh,
                               const float* __restrict__ Wt) {
    __shared__ float tile[32][33];
    const int k0 = blockIdx.x * 32, n0 = blockIdx.y * 32;
    const int tx = threadIdx.x, ty = threadIdx.y;
    const int n = n0 + tx;
#pragma unroll
    for (int j = 0; j < 4; ++j) {
        int k = k0 + ty + j * 8;
        float v = 0.f;
        if (n < Hh) v = Wh[(size_t)k * Hh + n];
        else if (n < 2 * Hh) v = Wt[(size_t)k * Hh + (n - Hh)];
        tile[tx][ty + j * 8] = v;  // [n_local][k_local]
    }
    __syncthreads();
#pragma unroll
    for (int j = 0; j < 4; ++j) {
        int nn = n0 + ty + j * 8, k = k0 + tx;
        float v = tile[ty + j * 8][tx];
        __nv_bfloat16 h, l;
        bsplit(v, h, l);
        g_Wthi[(size_t)nn * Dd + k] = h;
        g_Wtlo[(size_t)nn * Dd + k] = l;
    }
}

// ---------------------------------------------------------------------------
// Ut transpose+split (+reduce fold partials): Ueff[k=i][n=j] -> Ut[n][k]
// hi/lo [256,224], zero-padded. Grid (KP/32, NPU/32), block (32,8).
// ---------------------------------------------------------------------------
__global__ void split_ut_kernel() {
    __shared__ float tile[32][33];
    const int k0 = blockIdx.x * 32, n0 = blockIdx.y * 32;
    const int tx = threadIdx.x, ty = threadIdx.y;
    const int n = n0 + tx;
#pragma unroll
    for (int j = 0; j < 4; ++j) {
        int k = k0 + ty + j * 8;
        float v = 0.f;
        if (n < Hh && k < Hh) {
            size_t o = (size_t)k * Hh + n;
#pragma unroll
            for (int p = 0; p < NFOLD; ++p) v += g_Upart[p * HH2 + o];
        }
        tile[tx][ty + j * 8] = v;
    }
    __syncthreads();
#pragma unroll
    for (int j = 0; j < 4; ++j) {
        int nn = n0 + ty + j * 8, k = k0 + tx;
        float v = tile[ty + j * 8][tx];
        __nv_bfloat16 h, l;
        bsplit(v, h, l);
        g_Uthi[(size_t)nn * KP + k] = h;
        g_Utlo[(size_t)nn * KP + k] = l;
    }
}

// head planes: zero k-pad cols 200..223 with 16B stores.
__global__ void zero_hpad_kernel() {
    int gid = blockIdx.x * 256 + threadIdx.x;
    if (gid >= BSROWS * 3) return;
    int row = gid / 3, c = Hh + (gid % 3) * 8;
    const uint4 z = make_uint4(0, 0, 0, 0);
    *(uint4*)(g_hhi + (size_t)row * KP + c) = z;
    *(uint4*)(g_hlo + (size_t)row * KP + c) = z;
}

// ---------------------------------------------------------------------------
// MMA primitives
// ---------------------------------------------------------------------------
__device__ __forceinline__ void ldsm4(unsigned r[4], unsigned a) {
    asm volatile(
        "ldmatrix.sync.aligned.m8n8.x4.shared.b16 {%0,%1,%2,%3}, [%4];\n"
        : "=r"(r[0]), "=r"(r[1]), "=r"(r[2]), "=r"(r[3])
        : "r"(a));
}
__device__ __forceinline__ void mma_bf16(float c[4], const unsigned a[4],
                                         const unsigned b[2]) {
    asm volatile(
        "mma.sync.aligned.m16n8k16.row.col.f32.bf16.bf16.f32 "
        "{%0,%1,%2,%3}, {%4,%5,%6,%7}, {%8,%9}, {%0,%1,%2,%3};\n"
        : "+f"(c[0]), "+f"(c[1]), "+f"(c[2]), "+f"(c[3])
        : "r"(a[0]), "r"(a[1]), "r"(a[2]), "r"(a[3]), "r"(b[0]), "r"(b[1]));
}

// XOR swizzle: rows are 64B (BK=32 bf16). chunk = 16B unit index (0..3).
__device__ __forceinline__ unsigned swz(int row, int c) {
    return (unsigned)(row * 64 + ((c ^ ((row >> 1) & 3)) << 4));
}

// ---------------------------------------------------------------------------
// Unified bf16x3 MMA GEMM.  C = Ahi*Bhi + Ahi*Blo + Alo*Bhi
// A gmem: row-major [m][k] (hi/lo planes), B gmem: [n][k] (hi/lo planes).
// MODE 0: proj epilogue (bias+relu -> split to g_h*/g_t*)
// MODE 1: gemm_m epilogue (split to g_M*, zero k-pad)
// MODE 2: scores epilogue ((v + bd) / sqrt(200) -> fp32 out, batched by z)
// ---------------------------------------------------------------------------
template <int BM, int MODE>
__global__ __launch_bounds__(256) void mma_gemm_kernel(
    const __nv_bfloat16* __restrict__ Ahi, const __nv_bfloat16* __restrict__ Alo,
    int lda,
    const __nv_bfloat16* __restrict__ Bhi, const __nv_bfloat16* __restrict__ Blo,
    int ldb, int ktiles,
    const float* __restrict__ bias_h, const float* __restrict__ bias_t,
    float* __restrict__ outf, const float* __restrict__ bdown) {
    constexpr int WM = BM / 32;
    constexpr int WN = 8 / WM;
    constexpr int WNT = 64 / WN;
    constexpr int NSUB = WNT / 8;
    constexpr int ABYTES = BM * 64;
    constexpr int BBYTES = 64 * 64;
    constexpr int STAGE = 2 * ABYTES + 2 * BBYTES;
    constexpr int A_TOT = 2 * BM * 4;
    constexpr int A_IT = A_TOT / 256;

    __shared__ __align__(16) unsigned char smem[2 * STAGE];

    const int t = threadIdx.x;
    const int lane = t & 31, warp = t >> 5;
    const int m0 = blockIdx.y * BM;
    const int n0 = blockIdx.x * 64;
    const int wm = (warp % WM) * 32;
    const int wn = (warp / WM) * WNT;

    if (MODE == 2) {
        size_t ofs = (size_t)blockIdx.z * SQ;
        Ahi += ofs * lda; Alo += ofs * lda;
        Bhi += ofs * ldb; Blo += ofs * ldb;
    }

    const __nv_bfloat16* aptr[A_IT];
    unsigned aoff[A_IT];
#pragma unroll
    for (int i = 0; i < A_IT; ++i) {
        int ca = t + i * 256;
        int pl = ca / (BM * 4);
        int rem = ca - pl * (BM * 4);
        int row = rem >> 2, c = rem & 3;
        aptr[i] = (pl ? Alo : Ahi) + (size_t)(m0 + row) * lda + c * 8;
        aoff[i] = pl * ABYTES + swz(row, c);
    }
    const __nv_bfloat16* bptr[2];
    unsigned boff[2];
#pragma unroll
    for (int i = 0; i < 2; ++i) {
        int cb = t + i * 256;
        int pl = cb >> 8;
        int rem = cb & 255;
        int row = rem >> 2, c = rem & 3;
        bptr[i] = (pl ? Blo : Bhi) + (size_t)(n0 + row) * ldb + c * 8;
        boff[i] = 2 * ABYTES + pl * BBYTES + swz(row, c);
    }

    const unsigned sbase = (unsigned)__cvta_generic_to_shared(smem);
    float acc[2][NSUB][4];
#pragma unroll
    for (int mi = 0; mi < 2; ++mi)
#pragma unroll
        for (int ni = 0; ni < NSUB; ++ni)
#pragma unroll
            for (int r = 0; r < 4; ++r) acc[mi][ni][r] = 0.f;

    uint4 ra[A_IT], rb[2];
#pragma unroll
    for (int i = 0; i < A_IT; ++i) ra[i] = *(const uint4*)aptr[i];
#pragma unroll
    for (int i = 0; i < 2; ++i) rb[i] = *(const uint4*)bptr[i];
#pragma unroll
    for (int i = 0; i < A_IT; ++i) *(uint4*)(smem + aoff[i]) = ra[i];
#pragma unroll
    for (int i = 0; i < 2; ++i) *(uint4*)(smem + boff[i]) = rb[i];
    __syncthreads();

    auto compute = [&](int buf) {
        unsigned bb = sbase + buf * STAGE;
#pragma unroll
        for (int s = 0; s < 2; ++s) {
            unsigned ah[2][4], al[2][4], bh[NSUB][2], bl[NSUB][2];
            {
                int row0 = wm + (lane & 15);
                int c = 2 * s + (lane >> 4);
#pragma unroll
                for (int mi = 0; mi < 2; ++mi) {
                    unsigned sa = swz(row0 + mi * 16, c);
                    ldsm4(ah[mi], bb + sa);
                    ldsm4(al[mi], bb + ABYTES + sa);
                }
            }
            {
                int rbase = wn + (lane & 7) + ((lane >> 4) << 3);
                int c = 2 * s + ((lane >> 3) & 1);
#pragma unroll
                for (int p = 0; p < NSUB / 2; ++p) {
                    unsigned sb = swz(rbase + p * 16, c);
                    unsigned tmp[4];
                    ldsm4(tmp, bb + 2 * ABYTES + sb);
                    bh[2 * p][0] = tmp[0]; bh[2 * p][1] = tmp[1];
                    bh[2 * p + 1][0] = tmp[2]; bh[2 * p + 1][1] = tmp[3];
                    ldsm4(tmp, bb + 2 * ABYTES + BBYTES + sb);
                    bl[2 * p][0] = tmp[0]; bl[2 * p][1] = tmp[1];
                    bl[2 * p + 1][0] = tmp[2]; bl[2 * p + 1][1] = tmp[3];
                }
            }
#pragma unroll
            for (int mi = 0; mi < 2; ++mi)
#pragma unroll
                for (int ni = 0; ni < NSUB; ++ni)
                    mma_bf16(acc[mi][ni], ah[mi], bh[ni]);
#pragma unroll
            for (int mi = 0; mi < 2; ++mi)
#pragma unroll
                for (int ni = 0; ni < NSUB; ++ni)
                    mma_bf16(acc[mi][ni], ah[mi], bl[ni]);
#pragma unroll
            for (int mi = 0; mi < 2; ++mi)
#pragma unroll
                for (int ni = 0; ni < NSUB; ++ni)
                    mma_bf16(acc[mi][ni], al[mi], bh[ni]);
        }
    };

    int buf = 0;
#pragma unroll 1
    for (int kt = 1; kt < ktiles; ++kt) {
#pragma unroll
        for (int i = 0; i < A_IT; ++i)
            ra[i] = *(const uint4*)(aptr[i] + kt * 32);
#pragma unroll
        for (int i = 0; i < 2; ++i)
            rb[i] = *(const uint4*)(bptr[i] + kt * 32);
        compute(buf);
        int nb = buf ^ 1;
        unsigned sb = nb * STAGE;
#pragma unroll
        for (int i = 0; i < A_IT; ++i) *(uint4*)(smem + sb + aoff[i]) = ra[i];
#pragma unroll
        for (int i = 0; i < 2; ++i) *(uint4*)(smem + sb + boff[i]) = rb[i];
        __syncthreads();
        buf = nb;
    }
    compute(buf);

    const float rs = 0.070710678118654752f;
    float bd = 0.f;
    if (MODE == 2) bd = __ldg(bdown);

#pragma unroll
    for (int mi = 0; mi < 2; ++mi) {
#pragma unroll
        for (int ni = 0; ni < NSUB; ++ni) {
#pragma unroll
            for (int rp = 0; rp < 2; ++rp) {
                int row = m0 + wm + mi * 16 + (lane >> 2) + rp * 8;
                int col = n0 + wn + ni * 8 + 2 * (lane & 3);
                float v0 = acc[mi][ni][rp * 2];
                float v1 = acc[mi][ni][rp * 2 + 1];
                if (MODE == 0) {
                    if (col < Hh) {
                        v0 = fmaxf(v0 + __ldg(&bias_h[col]), 0.f);
                        v1 = fmaxf(v1 + __ldg(&bias_h[col + 1]), 0.f);
                        __nv_bfloat16 h0, l0, h1, l1;
                        bsplit(v0, h0, l0);
                        bsplit(v1, h1, l1);
                        size_t o = (size_t)row * KP + col;
                        *(__nv_bfloat162*)(g_hhi + o) = __halves2bfloat162(h0, h1);
                        *(__nv_bfloat162*)(g_hlo + o) = __halves2bfloat162(l0, l1);
                    } else {
                        int c = col - Hh;
                        if (c < KP) {
                            if (col < 2 * Hh) {
                                v0 = fmaxf(v0 + __ldg(&bias_t[c]), 0.f);
                                v1 = fmaxf(v1 + __ldg(&bias_t[c + 1]), 0.f);
                            } else {
                                v0 = 0.f;
                                v1 = 0.f;
                            }
                            __nv_bfloat16 h0, l0, h1, l1;
                            bsplit(v0, h0, l0);
                            bsplit(v1, h1, l1);
                            size_t o = (size_t)row * KP + c;
                            *(__nv_bfloat162*)(g_thi + o) =
                                __halves2bfloat162(h0, h1);
                            *(__nv_bfloat162*)(g_tlo + o) =
                                __halves2bfloat162(l0, l1);
                        }
                    }
                } else if (MODE == 1) {
                    if (col < KP) {
                        if (col >= Hh) { v0 = 0.f; v1 = 0.f; }
                        __nv_bfloat16 h0, l0, h1, l1;
                        bsplit(v0, h0, l0);
                        bsplit(v1, h1, l1);
                        size_t o = (size_t)row * KP + col;
                        *(__nv_bfloat162*)(g_Mhi + o) = __halves2bfloat162(h0, h1);
                        *(__nv_bfloat162*)(g_Mlo + o) = __halves2bfloat162(l0, l1);
                    }
                } else {
                    float2 o;
                    o.x = (v0 + bd) * rs;
                    o.y = (v1 + bd) * rs;
                    *(float2*)(outf + (size_t)blockIdx.z * SQ * SQ +
                               (size_t)row * SQ + col) = o;
                }
            }
        }
    }
}

// ---------------------------------------------------------------------------
// Inputs (metadata order): x, W_head, b_head, W_tail, b_tail, U, W_down, b_down
// ---------------------------------------------------------------------------
extern "C" void kernel_launch(void* const* d_in, const int* in_sizes, int n_in,
                              void* d_out, int out_size) {
    const float* x      = (const float*)d_in[0];
    const float* W_head = (const float*)d_in[1];
    const float* b_head = (const float*)d_in[2];
    const float* W_tail = (const float*)d_in[3];
    const float* b_tail = (const float*)d_in[4];
    const float* U      = (const float*)d_in[5];
    const float* W_down = (const float*)d_in[6];
    const float* b_down = (const float*)d_in[7];
    float* out = (float*)d_out;

    static __nv_bfloat16 *p_xhi, *p_xlo, *p_Wthi, *p_Wtlo, *p_Uthi, *p_Utlo;
    static __nv_bfloat16 *p_hhi, *p_hlo, *p_thi, *p_tlo, *p_Mhi, *p_Mlo;
    static cudaStream_t s1;
    static cudaEvent_t e_fork, e_join;
    static bool init = false;
    if (!init) {
        cudaGetSymbolAddress((void**)&p_xhi, g_xhi);
        cudaGetSymbolAddress((void**)&p_xlo, g_xlo);
        cudaGetSymbolAddress((void**)&p_Wthi, g_Wthi);
        cudaGetSymbolAddress((void**)&p_Wtlo, g_Wtlo);
        cudaGetSymbolAddress((void**)&p_Uthi, g_Uthi);
        cudaGetSymbolAddress((void**)&p_Utlo, g_Utlo);
        cudaGetSymbolAddress((void**)&p_hhi, g_hhi);
        cudaGetSymbolAddress((void**)&p_hlo, g_hlo);
        cudaGetSymbolAddress((void**)&p_thi, g_thi);
        cudaGetSymbolAddress((void**)&p_tlo, g_tlo);
        cudaGetSymbolAddress((void**)&p_Mhi, g_Mhi);
        cudaGetSymbolAddress((void**)&p_Mlo, g_Mlo);
        cudaStreamCreateWithFlags(&s1, cudaStreamNonBlocking);
        cudaEventCreateWithFlags(&e_fork, cudaEventDisableTiming);
        cudaEventCreateWithFlags(&e_join, cudaEventDisableTiming);
        init = true;
    }

    // fork: side stream runs the U-fold chain + pad zeroing (only needed
    // before gemm_m), overlapping the main-stream split_x/split_w/proj.
    cudaEventRecord(e_fork, 0);
    cudaStreamWaitEvent(s1, e_fork, 0);

    fold_u_kernel<<<dim3((HH2 + 255) / 256, NFOLD), 256, 0, s1>>>(U, W_down);
    split_ut_kernel<<<dim3(KP / 32, NPU / 32), dim3(32, 8), 0, s1>>>();
    zero_hpad_kernel<<<(BSROWS * 3 + 255) / 256, 256, 0, s1>>>();
    cudaEventRecord(e_join, s1);

    // main stream
    split_x_kernel<<<BSROWS * Dd / 8 / 256, 256>>>(x);
    split_w_kernel<<<dim3(Dd / 32, NPW / 32), dim3(32, 8)>>>(W_head, W_tail);

    // proj: [2048x768] x [448x768]^T -> head/tail (bias+relu, split)
    mma_gemm_kernel<128, 0><<<dim3(NPW / 64, BSROWS / 128), 256>>>(
        p_xhi, p_xlo, Dd, p_Wthi, p_Wtlo, Dd, Dd / 32, b_head, b_tail,
        nullptr, nullptr);

    cudaStreamWaitEvent(0, e_join, 0);  // join before gemm_m needs Ut + pads

    // M = head @ Ueff : [2048x224] x [256x224]^T
    mma_gemm_kernel<64, 1><<<dim3(NPU / 64, BSROWS / 64), 256>>>(
        p_hhi, p_hlo, KP, p_Uthi, p_Utlo, KP, KP / 32, nullptr, nullptr,
        nullptr, nullptr);

    // scores[b] = (M_b @ tail_b^T + b_down) / sqrt(200)
    mma_gemm_kernel<128, 2><<<dim3(SQ / 64, SQ / 128, NB), 256>>>(
        p_Mhi, p_Mlo, KP, p_thi, p_tlo, KP, KP / 32, nullptr, nullptr, out,
        b_down);
}

// round 5
// speedup vs baseline: 2.8006x; 1.0179x over previous
#include <cuda_runtime.h>
#include <cuda_bf16.h>

#define Hh 200
#define Dd 768
#define BSROWS 2048   // B*S
#define SQ 512
#define NB 4
#define HH2 (Hh * Hh)
#define KP 224        // padded K for the H-sized contraction dims (7 * 32)
#define NPW 448       // padded N rows for Wt (7 * 64)
#define NPU 256       // padded N rows for Ut (4 * 64)
#define NFOLD 8       // o-split for the U fold

// ---------------------------------------------------------------------------
// Scratch (all __device__ globals; no allocation)
// ---------------------------------------------------------------------------
__device__ float g_Upart[NFOLD * HH2];
__device__ __nv_bfloat16 g_Wthi[NPW * Dd], g_Wtlo[NPW * Dd];
__device__ __nv_bfloat16 g_Uthi[NPU * KP], g_Utlo[NPU * KP];
__device__ __nv_bfloat16 g_hhi[BSROWS * KP], g_hlo[BSROWS * KP];
__device__ __nv_bfloat16 g_thi[BSROWS * KP], g_tlo[BSROWS * KP];
__device__ __nv_bfloat16 g_Mhi[BSROWS * KP], g_Mlo[BSROWS * KP];

__device__ __forceinline__ void bsplit(float v, __nv_bfloat16& h,
                                       __nv_bfloat16& l) {
    h = __float2bfloat16(v);
    l = __float2bfloat16(v - __bfloat162float(h));
}

// ---------------------------------------------------------------------------
// Fold partials: Upart[p][i,j] = sum_{o in slice p} U[o,i,j] * W_down[o]
// ---------------------------------------------------------------------------
__global__ void fold_u_kernel(const float* __restrict__ U,
                              const float* __restrict__ W_down) {
    int idx = blockIdx.x * 256 + threadIdx.x;
    if (idx >= HH2) return;
    int o0 = blockIdx.y * 25;
    const float* p = U + (size_t)o0 * HH2 + idx;
    const float* w = W_down + o0;
    float a0 = 0.f, a1 = 0.f, a2 = 0.f, a3 = 0.f, a4 = 0.f;
#pragma unroll
    for (int u = 0; u < 25; u += 5) {
        a0 = fmaf(p[(size_t)(u + 0) * HH2], __ldg(w + u + 0), a0);
        a1 = fmaf(p[(size_t)(u + 1) * HH2], __ldg(w + u + 1), a1);
        a2 = fmaf(p[(size_t)(u + 2) * HH2], __ldg(w + u + 2), a2);
        a3 = fmaf(p[(size_t)(u + 3) * HH2], __ldg(w + u + 3), a3);
        a4 = fmaf(p[(size_t)(u + 4) * HH2], __ldg(w + u + 4), a4);
    }
    g_Upart[(size_t)blockIdx.y * HH2 + idx] = ((a0 + a1) + (a2 + a3)) + a4;
}

// ---------------------------------------------------------------------------
// W transpose+split: [768,200]x2 -> [448,768] hi/lo, smem-tiled.
// ---------------------------------------------------------------------------
__global__ void split_w_kernel(const float* __restrict__ Wh,
                               const float* __restrict__ Wt) {
    __shared__ float tile[32][33];
    const int k0 = blockIdx.x * 32, n0 = blockIdx.y * 32;
    const int tx = threadIdx.x, ty = threadIdx.y;
    const int n = n0 + tx;
#pragma unroll
    for (int j = 0; j < 4; ++j) {
        int k = k0 + ty + j * 8;
        float v = 0.f;
        if (n < Hh) v = Wh[(size_t)k * Hh + n];
        else if (n < 2 * Hh) v = Wt[(size_t)k * Hh + (n - Hh)];
        tile[tx][ty + j * 8] = v;  // [n_local][k_local]
    }
    __syncthreads();
#pragma unroll
    for (int j = 0; j < 4; ++j) {
        int nn = n0 + ty + j * 8, k = k0 + tx;
        float v = tile[ty + j * 8][tx];
        __nv_bfloat16 h, l;
        bsplit(v, h, l);
        g_Wthi[(size_t)nn * Dd + k] = h;
        g_Wtlo[(size_t)nn * Dd + k] = l;
    }
}

// ---------------------------------------------------------------------------
// Ut transpose+split (+reduce fold partials): Ueff[k=i][n=j] -> Ut[n][k]
// ---------------------------------------------------------------------------
__global__ void split_ut_kernel() {
    __shared__ float tile[32][33];
    const int k0 = blockIdx.x * 32, n0 = blockIdx.y * 32;
    const int tx = threadIdx.x, ty = threadIdx.y;
    const int n = n0 + tx;
#pragma unroll
    for (int j = 0; j < 4; ++j) {
        int k = k0 + ty + j * 8;
        float v = 0.f;
        if (n < Hh && k < Hh) {
            size_t o = (size_t)k * Hh + n;
#pragma unroll
            for (int p = 0; p < NFOLD; ++p) v += g_Upart[p * HH2 + o];
        }
        tile[tx][ty + j * 8] = v;
    }
    __syncthreads();
#pragma unroll
    for (int j = 0; j < 4; ++j) {
        int nn = n0 + ty + j * 8, k = k0 + tx;
        float v = tile[ty + j * 8][tx];
        __nv_bfloat16 h, l;
        bsplit(v, h, l);
        g_Uthi[(size_t)nn * KP + k] = h;
        g_Utlo[(size_t)nn * KP + k] = l;
    }
}

// head planes: zero k-pad cols 200..223 with 16B stores.
__global__ void zero_hpad_kernel() {
    int gid = blockIdx.x * 256 + threadIdx.x;
    if (gid >= BSROWS * 3) return;
    int row = gid / 3, c = Hh + (gid % 3) * 8;
    const uint4 z = make_uint4(0, 0, 0, 0);
    *(uint4*)(g_hhi + (size_t)row * KP + c) = z;
    *(uint4*)(g_hlo + (size_t)row * KP + c) = z;
}

// ---------------------------------------------------------------------------
// MMA primitives
// ---------------------------------------------------------------------------
__device__ __forceinline__ void ldsm4(unsigned r[4], unsigned a) {
    asm volatile(
        "ldmatrix.sync.aligned.m8n8.x4.shared.b16 {%0,%1,%2,%3}, [%4];\n"
        : "=r"(r[0]), "=r"(r[1]), "=r"(r[2]), "=r"(r[3])
        : "r"(a));
}
__device__ __forceinline__ void mma_bf16(float c[4], const unsigned a[4],
                                         const unsigned b[2]) {
    asm volatile(
        "mma.sync.aligned.m16n8k16.row.col.f32.bf16.bf16.f32 "
        "{%0,%1,%2,%3}, {%4,%5,%6,%7}, {%8,%9}, {%0,%1,%2,%3};\n"
        : "+f"(c[0]), "+f"(c[1]), "+f"(c[2]), "+f"(c[3])
        : "r"(a[0]), "r"(a[1]), "r"(a[2]), "r"(a[3]), "r"(b[0]), "r"(b[1]));
}

// XOR swizzle: rows are 64B (BK=32 bf16). chunk = 16B unit index (0..3).
__device__ __forceinline__ unsigned swz(int row, int c) {
    return (unsigned)(row * 64 + ((c ^ ((row >> 1) & 3)) << 4));
}

// ---------------------------------------------------------------------------
// Unified bf16x3 MMA GEMM (BM=64).  C = Ahi*Bhi + Ahi*Blo + Alo*Bhi
// AF32: A is fp32 in gmem; split to hi/lo planes on the fly during staging.
// else: A gmem is row-major [m][k] hi/lo bf16 planes.
// B gmem: [n][k] hi/lo bf16 planes.
// MODE 0: proj epilogue (bias+relu -> split to g_h*/g_t*)
// MODE 1: gemm_m epilogue (split to g_M*, zero k-pad)
// MODE 2: scores epilogue ((v + bd) / sqrt(200) -> fp32 out, batched by z)
// ---------------------------------------------------------------------------
template <int MODE, bool AF32>
__global__ __launch_bounds__(256) void mma_gemm_kernel(
    const void* __restrict__ Ahi_, const void* __restrict__ Alo_, int lda,
    const __nv_bfloat16* __restrict__ Bhi, const __nv_bfloat16* __restrict__ Blo,
    int ldb, int ktiles,
    const float* __restrict__ bias_h, const float* __restrict__ bias_t,
    float* __restrict__ outf, const float* __restrict__ bdown) {
    constexpr int BM = 64;
    constexpr int WM = 2, WN = 4, WNT = 16, NSUB = 2;
    constexpr int ABYTES = BM * 64;      // per plane per stage
    constexpr int BBYTES = 64 * 64;
    constexpr int STAGE = 2 * ABYTES + 2 * BBYTES;

    __shared__ __align__(16) unsigned char smem[2 * STAGE];

    const int t = threadIdx.x;
    const int lane = t & 31, warp = t >> 5;
    const int m0 = blockIdx.y * BM;
    const int n0 = blockIdx.x * 64;
    const int wm = (warp % WM) * 32;
    const int wn = (warp / WM) * WNT;

    const float* Af = (const float*)Ahi_;
    const __nv_bfloat16* Ahi = (const __nv_bfloat16*)Ahi_;
    const __nv_bfloat16* Alo = (const __nv_bfloat16*)Alo_;
    if (MODE == 2) {
        size_t ofs = (size_t)blockIdx.z * SQ;
        Ahi += ofs * lda; Alo += ofs * lda;
        Bhi += ofs * ldb; Blo += ofs * ldb;
    }

    // ---- staging descriptors ----
    // AF32: one 32B fp32 chunk per thread -> hi+lo 16B smem chunks.
    const float* axp = nullptr;
    unsigned aoh = 0, aol = 0;
    // bf16 planes: 2 chunks per thread.
    const __nv_bfloat16* aptr[2];
    unsigned aoff[2];
    if (AF32) {
        int row = t >> 2, c = t & 3;
        axp = Af + (size_t)(m0 + row) * lda + c * 8;
        aoh = swz(row, c);
        aol = ABYTES + swz(row, c);
    } else {
#pragma unroll
        for (int i = 0; i < 2; ++i) {
            int ca = t + i * 256;
            int pl = ca / (BM * 4);
            int rem = ca - pl * (BM * 4);
            int row = rem >> 2, c = rem & 3;
            aptr[i] = (pl ? Alo : Ahi) + (size_t)(m0 + row) * lda + c * 8;
            aoff[i] = pl * ABYTES + swz(row, c);
        }
    }
    const __nv_bfloat16* bptr[2];
    unsigned boff[2];
#pragma unroll
    for (int i = 0; i < 2; ++i) {
        int cb = t + i * 256;
        int pl = cb >> 8;
        int rem = cb & 255;
        int row = rem >> 2, c = rem & 3;
        bptr[i] = (pl ? Blo : Bhi) + (size_t)(n0 + row) * ldb + c * 8;
        boff[i] = 2 * ABYTES + pl * BBYTES + swz(row, c);
    }

    const unsigned sbase = (unsigned)__cvta_generic_to_shared(smem);
    float acc[2][NSUB][4];
#pragma unroll
    for (int mi = 0; mi < 2; ++mi)
#pragma unroll
        for (int ni = 0; ni < NSUB; ++ni)
#pragma unroll
            for (int r = 0; r < 4; ++r) acc[mi][ni][r] = 0.f;

    float4 rf0, rf1;
    uint4 ra[2], rb[2];

    auto load_a = [&](int kt) {
        if (AF32) {
            rf0 = *(const float4*)(axp + kt * 32);
            rf1 = *(const float4*)(axp + kt * 32 + 4);
        } else {
#pragma unroll
            for (int i = 0; i < 2; ++i)
                ra[i] = *(const uint4*)(aptr[i] + kt * 32);
        }
    };
    auto store_a = [&](unsigned sb) {
        if (AF32) {
            float v[8] = {rf0.x, rf0.y, rf0.z, rf0.w,
                          rf1.x, rf1.y, rf1.z, rf1.w};
            union { __nv_bfloat16 h[8]; uint4 u; } H, L;
#pragma unroll
            for (int j = 0; j < 8; ++j) bsplit(v[j], H.h[j], L.h[j]);
            *(uint4*)(smem + sb + aoh) = H.u;
            *(uint4*)(smem + sb + aol) = L.u;
        } else {
#pragma unroll
            for (int i = 0; i < 2; ++i)
                *(uint4*)(smem + sb + aoff[i]) = ra[i];
        }
    };

    load_a(0);
#pragma unroll
    for (int i = 0; i < 2; ++i) rb[i] = *(const uint4*)bptr[i];
    store_a(0);
#pragma unroll
    for (int i = 0; i < 2; ++i) *(uint4*)(smem + boff[i]) = rb[i];
    __syncthreads();

    auto compute = [&](int buf) {
        unsigned bb = sbase + buf * STAGE;
#pragma unroll
        for (int s = 0; s < 2; ++s) {
            unsigned ah[2][4], al[2][4], bh[NSUB][2], bl[NSUB][2];
            {
                int row0 = wm + (lane & 15);
                int c = 2 * s + (lane >> 4);
#pragma unroll
                for (int mi = 0; mi < 2; ++mi) {
                    unsigned sa = swz(row0 + mi * 16, c);
                    ldsm4(ah[mi], bb + sa);
                    ldsm4(al[mi], bb + ABYTES + sa);
                }
            }
            {
                int rbase = wn + (lane & 7) + ((lane >> 4) << 3);
                int c = 2 * s + ((lane >> 3) & 1);
                unsigned sb = swz(rbase, c);
                unsigned tmp[4];
                ldsm4(tmp, bb + 2 * ABYTES + sb);
                bh[0][0] = tmp[0]; bh[0][1] = tmp[1];
                bh[1][0] = tmp[2]; bh[1][1] = tmp[3];
                ldsm4(tmp, bb + 2 * ABYTES + BBYTES + sb);
                bl[0][0] = tmp[0]; bl[0][1] = tmp[1];
                bl[1][0] = tmp[2]; bl[1][1] = tmp[3];
            }
#pragma unroll
            for (int mi = 0; mi < 2; ++mi)
#pragma unroll
                for (int ni = 0; ni < NSUB; ++ni)
                    mma_bf16(acc[mi][ni], ah[mi], bh[ni]);
#pragma unroll
            for (int mi = 0; mi < 2; ++mi)
#pragma unroll
                for (int ni = 0; ni < NSUB; ++ni)
                    mma_bf16(acc[mi][ni], ah[mi], bl[ni]);
#pragma unroll
            for (int mi = 0; mi < 2; ++mi)
#pragma unroll
                for (int ni = 0; ni < NSUB; ++ni)
                    mma_bf16(acc[mi][ni], al[mi], bh[ni]);
        }
    };

    int buf = 0;
#pragma unroll 1
    for (int kt = 1; kt < ktiles; ++kt) {
        load_a(kt);
#pragma unroll
        for (int i = 0; i < 2; ++i)
            rb[i] = *(const uint4*)(bptr[i] + kt * 32);
        compute(buf);
        int nb = buf ^ 1;
        unsigned sb = nb * STAGE;
        store_a(sb);
#pragma unroll
        for (int i = 0; i < 2; ++i) *(uint4*)(smem + sb + boff[i]) = rb[i];
        __syncthreads();
        buf = nb;
    }
    compute(buf);

    // ---------------- epilogue ----------------
    const float rs = 0.070710678118654752f;
    float bd = 0.f;
    if (MODE == 2) bd = __ldg(bdown);

#pragma unroll
    for (int mi = 0; mi < 2; ++mi) {
#pragma unroll
        for (int ni = 0; ni < NSUB; ++ni) {
#pragma unroll
            for (int rp = 0; rp < 2; ++rp) {
                int row = m0 + wm + mi * 16 + (lane >> 2) + rp * 8;
                int col = n0 + wn + ni * 8 + 2 * (lane & 3);
                float v0 = acc[mi][ni][rp * 2];
                float v1 = acc[mi][ni][rp * 2 + 1];
                if (MODE == 0) {
                    if (col < Hh) {
                        v0 = fmaxf(v0 + __ldg(&bias_h[col]), 0.f);
                        v1 = fmaxf(v1 + __ldg(&bias_h[col + 1]), 0.f);
                        __nv_bfloat16 h0, l0, h1, l1;
                        bsplit(v0, h0, l0);
                        bsplit(v1, h1, l1);
                        size_t o = (size_t)row * KP + col;
                        *(__nv_bfloat162*)(g_hhi + o) = __halves2bfloat162(h0, h1);
                        *(__nv_bfloat162*)(g_hlo + o) = __halves2bfloat162(l0, l1);
                    } else {
                        int c = col - Hh;
                        if (c < KP) {
                            if (col < 2 * Hh) {
                                v0 = fmaxf(v0 + __ldg(&bias_t[c]), 0.f);
                                v1 = fmaxf(v1 + __ldg(&bias_t[c + 1]), 0.f);
                            } else {
                                v0 = 0.f;
                                v1 = 0.f;
                            }
                            __nv_bfloat16 h0, l0, h1, l1;
                            bsplit(v0, h0, l0);
                            bsplit(v1, h1, l1);
                            size_t o = (size_t)row * KP + c;
                            *(__nv_bfloat162*)(g_thi + o) =
                                __halves2bfloat162(h0, h1);
                            *(__nv_bfloat162*)(g_tlo + o) =
                                __halves2bfloat162(l0, l1);
                        }
                    }
                } else if (MODE == 1) {
                    if (col < KP) {
                        if (col >= Hh) { v0 = 0.f; v1 = 0.f; }
                        __nv_bfloat16 h0, l0, h1, l1;
                        bsplit(v0, h0, l0);
                        bsplit(v1, h1, l1);
                        size_t o = (size_t)row * KP + col;
                        *(__nv_bfloat162*)(g_Mhi + o) = __halves2bfloat162(h0, h1);
                        *(__nv_bfloat162*)(g_Mlo + o) = __halves2bfloat162(l0, l1);
                    }
                } else {
                    float2 o;
                    o.x = (v0 + bd) * rs;
                    o.y = (v1 + bd) * rs;
                    *(float2*)(outf + (size_t)blockIdx.z * SQ * SQ +
                               (size_t)row * SQ + col) = o;
                }
            }
        }
    }
}

// ---------------------------------------------------------------------------
// Inputs (metadata order): x, W_head, b_head, W_tail, b_tail, U, W_down, b_down
// ---------------------------------------------------------------------------
extern "C" void kernel_launch(void* const* d_in, const int* in_sizes, int n_in,
                              void* d_out, int out_size) {
    const float* x      = (const float*)d_in[0];
    const float* W_head = (const float*)d_in[1];
    const float* b_head = (const float*)d_in[2];
    const float* W_tail = (const float*)d_in[3];
    const float* b_tail = (const float*)d_in[4];
    const float* U      = (const float*)d_in[5];
    const float* W_down = (const float*)d_in[6];
    const float* b_down = (const float*)d_in[7];
    float* out = (float*)d_out;

    static __nv_bfloat16 *p_Wthi, *p_Wtlo, *p_Uthi, *p_Utlo;
    static __nv_bfloat16 *p_hhi, *p_hlo, *p_thi, *p_tlo, *p_Mhi, *p_Mlo;
    static cudaStream_t s1;
    static cudaEvent_t e_fork, e_join;
    static bool init = false;
    if (!init) {
        cudaGetSymbolAddress((void**)&p_Wthi, g_Wthi);
        cudaGetSymbolAddress((void**)&p_Wtlo, g_Wtlo);
        cudaGetSymbolAddress((void**)&p_Uthi, g_Uthi);
        cudaGetSymbolAddress((void**)&p_Utlo, g_Utlo);
        cudaGetSymbolAddress((void**)&p_hhi, g_hhi);
        cudaGetSymbolAddress((void**)&p_hlo, g_hlo);
        cudaGetSymbolAddress((void**)&p_thi, g_thi);
        cudaGetSymbolAddress((void**)&p_tlo, g_tlo);
        cudaGetSymbolAddress((void**)&p_Mhi, g_Mhi);
        cudaGetSymbolAddress((void**)&p_Mlo, g_Mlo);
        cudaStreamCreateWithFlags(&s1, cudaStreamNonBlocking);
        cudaEventCreateWithFlags(&e_fork, cudaEventDisableTiming);
        cudaEventCreateWithFlags(&e_join, cudaEventDisableTiming);
        init = true;
    }

    // fork: side stream runs the U-fold chain + pad zeroing (only needed
    // before gemm_m), overlapping the main-stream split_w/proj.
    cudaEventRecord(e_fork, 0);
    cudaStreamWaitEvent(s1, e_fork, 0);

    fold_u_kernel<<<dim3((HH2 + 255) / 256, NFOLD), 256, 0, s1>>>(U, W_down);
    split_ut_kernel<<<dim3(KP / 32, NPU / 32), dim3(32, 8), 0, s1>>>();
    zero_hpad_kernel<<<(BSROWS * 3 + 255) / 256, 256, 0, s1>>>();
    cudaEventRecord(e_join, s1);

    // main stream
    split_w_kernel<<<dim3(Dd / 32, NPW / 32), dim3(32, 8)>>>(W_head, W_tail);

    // proj: [2048x768](fp32, split on the fly) x [448x768]^T -> head/tail
    mma_gemm_kernel<0, true><<<dim3(NPW / 64, BSROWS / 64), 256>>>(
        x, nullptr, Dd, p_Wthi, p_Wtlo, Dd, Dd / 32, b_head, b_tail,
        nullptr, nullptr);

    cudaStreamWaitEvent(0, e_join, 0);  // join before gemm_m needs Ut + pads

    // M = head @ Ueff : [2048x224] x [256x224]^T
    mma_gemm_kernel<1, false><<<dim3(NPU / 64, BSROWS / 64), 256>>>(
        p_hhi, p_hlo, KP, p_Uthi, p_Utlo, KP, KP / 32, nullptr, nullptr,
        nullptr, nullptr);

    // scores[b] = (M_b @ tail_b^T + b_down) / sqrt(200)
    mma_gemm_kernel<2, false><<<dim3(SQ / 64, SQ / 64, NB), 256>>>(
        p_Mhi, p_Mlo, KP, p_thi, p_tlo, KP, KP / 32, nullptr, nullptr, out,
        b_down);
}